// round 2
// baseline (speedup 1.0000x reference)
#include <cuda_runtime.h>
#include <math.h>

typedef unsigned long long ULL;

#define CDIM   192
#define OC3    576
#define HWDIM  256
#define SHIFT  4
#define NWIN   4096

// ---- shared memory layout (floats) ----
// XS: x window / attention output, px-paired float2 [ch][p2], ch-stride 32 pairs = 12288 floats
// QS: qkv after dwconv, px-paired, ch-stride 66 floats (8B-aligned pairs)  = 576*66 = 38016 floats
// ST: GEMM chunk staging 64ch*64px (4096) overlapped with attn 6*1024 (6144) -> 6144 floats
#define XS_OFF 0
#define QS_OFF 12288
#define ST_OFF (12288 + 38016)
#define SMEM_FLOATS (12288 + 38016 + 6144)   // 56448 floats = 225792 bytes

// duplicated-weight tables: w stored transposed [c][oc] as (w,w) pairs
__device__ __align__(16) float2 g_qkv_wd[CDIM * OC3];
__device__ __align__(16) float2 g_proj_wd[CDIM * CDIM];

__global__ void prep_weights(const float* __restrict__ qkv_w,
                             const float* __restrict__ proj_w)
{
    int i = blockIdx.x * blockDim.x + threadIdx.x;
    if (i < CDIM * OC3) {
        int c = i / OC3, oc = i % OC3;
        float w = qkv_w[(size_t)oc * CDIM + c];
        g_qkv_wd[i] = make_float2(w, w);
    } else {
        int j = i - CDIM * OC3;
        if (j < CDIM * CDIM) {
            int c = j / CDIM, oc = j % CDIM;
            float w = proj_w[(size_t)oc * CDIM + c];
            g_proj_wd[j] = make_float2(w, w);
        }
    }
}

__device__ __forceinline__ void ffma2(ULL& d, ULL a, ULL b)
{
    asm("fma.rn.f32x2 %0, %1, %2, %0;" : "+l"(d) : "l"(a), "l"(b));
}
__device__ __forceinline__ ULL dup2(float a)
{
    ULL r; unsigned u = __float_as_uint(a);
    asm("mov.b64 %0, {%1, %1};" : "=l"(r) : "r"(u));
    return r;
}
__device__ __forceinline__ float2 asf2(ULL v)
{
    float2 f;
    f.x = __uint_as_float((unsigned)(v & 0xffffffffu));
    f.y = __uint_as_float((unsigned)(v >> 32));
    return f;
}

// 64-oc GEMM chunk: acc[4] (oc = ocb + (tid>>5)*4 + j), px-pair = tid&31.
// Wd: dup'd transposed weights, row stride ldw (float2 units). srcf: smem float2 [c][p2].
__device__ __forceinline__ void gemm64(const float2* __restrict__ Wd, int ldw, int ocb,
                                       const float* __restrict__ srcf, ULL* acc, int tid)
{
    const int po2 = tid & 31;
    const int ocg = tid >> 5;
    const float2* Wp = Wd + ocb + ocg * 4;
    acc[0] = acc[1] = acc[2] = acc[3] = 0ull;
    #pragma unroll 4
    for (int c = 0; c < CDIM; ++c) {
        ulonglong2 w0 = *(const ulonglong2*)(Wp);
        ulonglong2 w1 = *(const ulonglong2*)(Wp + 2);
        ULL xv = *(const ULL*)(srcf + (c * 32 + po2) * 2);
        ffma2(acc[0], w0.x, xv);
        ffma2(acc[1], w0.y, xv);
        ffma2(acc[2], w1.x, xv);
        ffma2(acc[3], w1.y, xv);
        Wp += ldw;
    }
}

__global__ __launch_bounds__(512, 1)
void win_attn_kernel(const float* __restrict__ x,
                     const float* __restrict__ dw_w,
                     const float* __restrict__ temperature,
                     float* __restrict__ out)
{
    extern __shared__ float smf[];
    float* xsf = smf + XS_OFF;
    float* qsf = smf + QS_OFF;
    float* stf = smf + ST_OFF;

    const int tid = threadIdx.x;
    const int win = blockIdx.x;
    const int b   = win >> 10;
    const int wh  = (win >> 5) & 31;
    const int ww  = win & 31;
    const int h0  = wh * 8 + SHIFT;
    const int w0  = ww * 8 + SHIFT;

    // ---- load x window (applies -SHIFT roll), px-paired: (p2, p2+32) ----
    for (int i = tid; i < CDIM * 32; i += 512) {
        const int ch = i >> 5, p2 = i & 31;
        const int gh  = (h0 + (p2 >> 3)) & 255;
        const int gh2 = (gh + 4) & 255;
        const int gw  = (w0 + (p2 & 7)) & 255;
        const float* base = x + (size_t)(b * CDIM + ch) * HWDIM * HWDIM;
        float2 v = make_float2(base[gh * HWDIM + gw], base[gh2 * HWDIM + gw]);
        *(float2*)(xsf + i * 2) = v;
    }
    __syncthreads();

    const int po2 = tid & 31;
    const int ocg = tid >> 5;
    const int pl  = tid & 63;
    const int cl0 = tid >> 6;          // 0..7
    const int rr0 = pl >> 3, cc0 = pl & 7;

    // ---- qkv 1x1 (576x192 GEMM) + depthwise 3x3, 9 chunks of 64 oc ----
    for (int chk = 0; chk < 9; ++chk) {
        const int ocb = chk * 64;
        ULL acc[4];
        gemm64(g_qkv_wd, OC3, ocb, xsf, acc, tid);
        #pragma unroll
        for (int j = 0; j < 4; ++j)
            *(ULL*)(stf + ((ocg * 4 + j) * 32 + po2) * 2) = acc[j];
        __syncthreads();

        // depthwise 3x3, zero-padded window; px-paired staging layout
        const int wout = ((rr0 & 3) * 8 + cc0) * 2 + (rr0 >> 2);
        for (int it = 0; it < 8; ++it) {
            const int lc = it * 8 + cl0;
            const int gc = ocb + lc;
            const float* wd = dw_w + gc * 9;
            const float* s  = stf + lc * 64;
            float a = 0.f;
            #pragma unroll
            for (int dr = -1; dr <= 1; ++dr) {
                const int rr = rr0 + dr;
                if (rr < 0 || rr > 7) continue;
                #pragma unroll
                for (int dc = -1; dc <= 1; ++dc) {
                    const int c2 = cc0 + dc;
                    if (c2 < 0 || c2 > 7) continue;
                    a += s[((rr & 3) * 8 + c2) * 2 + (rr >> 2)] * wd[(dr + 1) * 3 + dc + 1];
                }
            }
            qsf[gc * 66 + wout] = a;
        }
        __syncthreads();
    }

    // ---- channel attention: 2 warps per head (12 warps active) ----
    const int lane = tid & 31;
    const int widx = tid >> 5;
    float* aof = xsf;   // reuse x region for attention output

    if (widx < 12) {
        const int h = widx >> 1, sub = widx & 1;
        const float* qf = qsf + (h * 32) * 66;
        const float* kf = qsf + (CDIM + h * 32) * 66;
        const float temp = temperature[h];
        float* attn_s = stf + h * 1024;

        // cache k-row(channel=lane) packed; compute q/k norms
        ULL k2[32];
        float sq = 0.f, sk = 0.f;
        #pragma unroll
        for (int n2 = 0; n2 < 32; ++n2) {
            ULL kv = *(const ULL*)(kf + lane * 66 + n2 * 2);
            k2[n2] = kv;
            float2 kk = asf2(kv);
            sk += kk.x * kk.x + kk.y * kk.y;
            float2 qq = *(const float2*)(qf + lane * 66 + n2 * 2);
            sq += qq.x * qq.x + qq.y * qq.y;
        }
        const float rk = 1.f / fmaxf(sqrtf(sk), 1e-12f);
        const float rq = 1.f / fmaxf(sqrtf(sq), 1e-12f);

        for (int r = 0; r < 16; ++r) {
            const int r0 = sub * 16 + r;
            ULL a2 = 0ull;
            #pragma unroll
            for (int n2 = 0; n2 < 32; ++n2) {
                ULL qv = *(const ULL*)(qf + r0 * 66 + n2 * 2);   // broadcast
                ffma2(a2, qv, k2[n2]);
            }
            float2 av = asf2(a2);
            float a = av.x + av.y;
            const float rqr = __shfl_sync(0xffffffffu, rq, r0);
            a *= rqr * rk * temp;
            // softmax across lanes (lane == d)
            float m = a;
            #pragma unroll
            for (int o = 16; o; o >>= 1) m = fmaxf(m, __shfl_xor_sync(0xffffffffu, m, o));
            const float e = __expf(a - m);
            float s2 = e;
            #pragma unroll
            for (int o = 16; o; o >>= 1) s2 += __shfl_xor_sync(0xffffffffu, s2, o);
            attn_s[r0 * 32 + lane] = e / s2;
        }
    }
    __syncthreads();

    if (widx < 12) {
        const int h = widx >> 1, sub = widx & 1;
        const float* vf = qsf + (2 * CDIM + h * 32) * 66;
        const float* attn_s = stf + h * 1024;

        // cache v columns (px-pair = lane) packed
        ULL vc[32];
        #pragma unroll
        for (int d = 0; d < 32; ++d)
            vc[d] = *(const ULL*)(vf + d * 66 + lane * 2);

        for (int r = 0; r < 16; ++r) {
            const int r0 = sub * 16 + r;
            ULL o2 = 0ull;
            #pragma unroll
            for (int d = 0; d < 32; ++d) {
                ULL ad = dup2(attn_s[r0 * 32 + d]);   // broadcast + dup
                ffma2(o2, ad, vc[d]);
            }
            *(ULL*)(aof + ((h * 32 + r0) * 32 + lane) * 2) = o2;
        }
    }
    __syncthreads();

    // ---- project_out 1x1 (192x192 GEMM), 3 chunks of 64, store with +SHIFT roll ----
    for (int chk = 0; chk < 3; ++chk) {
        const int ocb = chk * 64;
        ULL acc[4];
        gemm64(g_proj_wd, CDIM, ocb, aof, acc, tid);
        const int gh  = (h0 + (po2 >> 3)) & 255;
        const int gh2 = (gh + 4) & 255;
        const int gw  = (w0 + (po2 & 7)) & 255;
        #pragma unroll
        for (int j = 0; j < 4; ++j) {
            const int oc = ocb + ocg * 4 + j;
            float2 v = asf2(acc[j]);
            float* base = out + (size_t)(b * CDIM + oc) * HWDIM * HWDIM;
            base[gh * HWDIM + gw]  = v.x;
            base[gh2 * HWDIM + gw] = v.y;
        }
    }
}

extern "C" void kernel_launch(void* const* d_in, const int* in_sizes, int n_in,
                              void* d_out, int out_size)
{
    const float* x           = (const float*)d_in[0];
    const float* qkv_w       = (const float*)d_in[1];
    const float* dw_w        = (const float*)d_in[2];
    const float* proj_w      = (const float*)d_in[3];
    const float* temperature = (const float*)d_in[4];
    float* out               = (float*)d_out;

    const int prep_n = CDIM * OC3 + CDIM * CDIM;
    prep_weights<<<(prep_n + 255) / 256, 256>>>(qkv_w, proj_w);

    const size_t smem_bytes = (size_t)SMEM_FLOATS * sizeof(float);
    cudaFuncSetAttribute(win_attn_kernel,
                         cudaFuncAttributeMaxDynamicSharedMemorySize,
                         (int)smem_bytes);
    win_attn_kernel<<<NWIN, 512, smem_bytes>>>(x, dw_w, temperature, out);
}

// round 3
// speedup vs baseline: 1.6418x; 1.6418x over previous
#include <cuda_runtime.h>
#include <math.h>

typedef unsigned long long ULL;

#define CDIM   192
#define OC3    576
#define HWDIM  256
#define SHIFT  4
#define NWIN   4096

// ---- shared memory layout (floats) ----
// XS: x window / attention output, px-paired float2 [ch][p2], ch-stride 32 pairs = 12288 floats
// QS: qkv after dwconv, px-paired, ch-stride 66 floats (8B-aligned pairs)  = 576*66 = 38016 floats
// ST: GEMM chunk staging 64ch*64px (4096) overlapped with attn 6*1024 (6144) -> 6144 floats
#define XS_OFF 0
#define QS_OFF 12288
#define ST_OFF (12288 + 38016)
#define SMEM_FLOATS (12288 + 38016 + 6144)   // 56448 floats = 225792 bytes

// duplicated-weight tables: w stored transposed [c][oc] as (w,w) pairs
__device__ __align__(16) float2 g_qkv_wd[CDIM * OC3];
__device__ __align__(16) float2 g_proj_wd[CDIM * CDIM];

__global__ void prep_weights(const float* __restrict__ qkv_w,
                             const float* __restrict__ proj_w)
{
    int i = blockIdx.x * blockDim.x + threadIdx.x;
    if (i < CDIM * OC3) {
        int c = i / OC3, oc = i % OC3;
        float w = qkv_w[(size_t)oc * CDIM + c];
        g_qkv_wd[i] = make_float2(w, w);
    } else {
        int j = i - CDIM * OC3;
        if (j < CDIM * CDIM) {
            int c = j / CDIM, oc = j % CDIM;
            float w = proj_w[(size_t)oc * CDIM + c];
            g_proj_wd[j] = make_float2(w, w);
        }
    }
}

__device__ __forceinline__ void ffma2(ULL& d, ULL a, ULL b)
{
    asm("fma.rn.f32x2 %0, %1, %2, %0;" : "+l"(d) : "l"(a), "l"(b));
}
__device__ __forceinline__ ULL dup2(float a)
{
    ULL r; unsigned u = __float_as_uint(a);
    asm("mov.b64 %0, {%1, %1};" : "=l"(r) : "r"(u));
    return r;
}
__device__ __forceinline__ float2 asf2(ULL v)
{
    float2 f;
    f.x = __uint_as_float((unsigned)(v & 0xffffffffu));
    f.y = __uint_as_float((unsigned)(v >> 32));
    return f;
}

// 64-oc GEMM chunk: acc[4] (oc = ocb + (tid>>5)*4 + j), px-pair = tid&31.
// Wd: dup'd transposed weights, row stride ldw (float2 units). srcf: smem float2 [c][p2].
__device__ __forceinline__ void gemm64(const float2* __restrict__ Wd, int ldw, int ocb,
                                       const float* __restrict__ srcf, ULL* acc, int tid)
{
    const int po2 = tid & 31;
    const int ocg = tid >> 5;
    const float2* Wp = Wd + ocb + ocg * 4;
    acc[0] = acc[1] = acc[2] = acc[3] = 0ull;
    #pragma unroll 4
    for (int c = 0; c < CDIM; ++c) {
        ulonglong2 w0 = *(const ulonglong2*)(Wp);
        ulonglong2 w1 = *(const ulonglong2*)(Wp + 2);
        ULL xv = *(const ULL*)(srcf + (c * 32 + po2) * 2);
        ffma2(acc[0], w0.x, xv);
        ffma2(acc[1], w0.y, xv);
        ffma2(acc[2], w1.x, xv);
        ffma2(acc[3], w1.y, xv);
        Wp += ldw;
    }
}

__global__ __launch_bounds__(512, 1)
void win_attn_kernel(const float* __restrict__ x,
                     const float* __restrict__ dw_w,
                     const float* __restrict__ temperature,
                     float* __restrict__ out)
{
    extern __shared__ float smf[];
    float* xsf = smf + XS_OFF;
    float* qsf = smf + QS_OFF;
    float* stf = smf + ST_OFF;

    const int tid = threadIdx.x;
    const int win = blockIdx.x;
    const int b   = win >> 10;
    const int wh  = (win >> 5) & 31;
    const int ww  = win & 31;
    const int h0  = wh * 8 + SHIFT;
    const int w0  = ww * 8 + SHIFT;

    // ---- load x window (applies -SHIFT roll), px-paired: (p2, p2+32) ----
    for (int i = tid; i < CDIM * 32; i += 512) {
        const int ch = i >> 5, p2 = i & 31;
        const int gh  = (h0 + (p2 >> 3)) & 255;
        const int gh2 = (gh + 4) & 255;
        const int gw  = (w0 + (p2 & 7)) & 255;
        const float* base = x + (size_t)(b * CDIM + ch) * HWDIM * HWDIM;
        float2 v = make_float2(base[gh * HWDIM + gw], base[gh2 * HWDIM + gw]);
        *(float2*)(xsf + i * 2) = v;
    }
    __syncthreads();

    const int po2 = tid & 31;
    const int ocg = tid >> 5;
    const int pl  = tid & 63;
    const int cl0 = tid >> 6;          // 0..7
    const int rr0 = pl >> 3, cc0 = pl & 7;

    // ---- qkv 1x1 (576x192 GEMM) + depthwise 3x3, 9 chunks of 64 oc ----
    for (int chk = 0; chk < 9; ++chk) {
        const int ocb = chk * 64;
        ULL acc[4];
        gemm64(g_qkv_wd, OC3, ocb, xsf, acc, tid);
        #pragma unroll
        for (int j = 0; j < 4; ++j)
            *(ULL*)(stf + ((ocg * 4 + j) * 32 + po2) * 2) = acc[j];
        __syncthreads();

        // depthwise 3x3, zero-padded window; px-paired staging layout
        const int wout = ((rr0 & 3) * 8 + cc0) * 2 + (rr0 >> 2);
        for (int it = 0; it < 8; ++it) {
            const int lc = it * 8 + cl0;
            const int gc = ocb + lc;
            const float* wd = dw_w + gc * 9;
            const float* s  = stf + lc * 64;
            float a = 0.f;
            #pragma unroll
            for (int dr = -1; dr <= 1; ++dr) {
                const int rr = rr0 + dr;
                if (rr < 0 || rr > 7) continue;
                #pragma unroll
                for (int dc = -1; dc <= 1; ++dc) {
                    const int c2 = cc0 + dc;
                    if (c2 < 0 || c2 > 7) continue;
                    a += s[((rr & 3) * 8 + c2) * 2 + (rr >> 2)] * wd[(dr + 1) * 3 + dc + 1];
                }
            }
            qsf[gc * 66 + wout] = a;
        }
        __syncthreads();
    }

    // ---- channel attention: 2 warps per head (12 warps active) ----
    const int lane = tid & 31;
    const int widx = tid >> 5;
    float* aof = xsf;   // reuse x region for attention output

    if (widx < 12) {
        const int h = widx >> 1, sub = widx & 1;
        const float* qf = qsf + (h * 32) * 66;
        const float* kf = qsf + (CDIM + h * 32) * 66;
        const float temp = temperature[h];
        float* attn_s = stf + h * 1024;

        // cache k-row(channel=lane) packed; compute q/k norms
        ULL k2[32];
        float sq = 0.f, sk = 0.f;
        #pragma unroll
        for (int n2 = 0; n2 < 32; ++n2) {
            ULL kv = *(const ULL*)(kf + lane * 66 + n2 * 2);
            k2[n2] = kv;
            float2 kk = asf2(kv);
            sk += kk.x * kk.x + kk.y * kk.y;
            float2 qq = *(const float2*)(qf + lane * 66 + n2 * 2);
            sq += qq.x * qq.x + qq.y * qq.y;
        }
        const float rk = 1.f / fmaxf(sqrtf(sk), 1e-12f);
        const float rq = 1.f / fmaxf(sqrtf(sq), 1e-12f);

        for (int r = 0; r < 16; ++r) {
            const int r0 = sub * 16 + r;
            ULL a2 = 0ull;
            #pragma unroll
            for (int n2 = 0; n2 < 32; ++n2) {
                ULL qv = *(const ULL*)(qf + r0 * 66 + n2 * 2);   // broadcast
                ffma2(a2, qv, k2[n2]);
            }
            float2 av = asf2(a2);
            float a = av.x + av.y;
            const float rqr = __shfl_sync(0xffffffffu, rq, r0);
            a *= rqr * rk * temp;
            // softmax across lanes (lane == d)
            float m = a;
            #pragma unroll
            for (int o = 16; o; o >>= 1) m = fmaxf(m, __shfl_xor_sync(0xffffffffu, m, o));
            const float e = __expf(a - m);
            float s2 = e;
            #pragma unroll
            for (int o = 16; o; o >>= 1) s2 += __shfl_xor_sync(0xffffffffu, s2, o);
            attn_s[r0 * 32 + lane] = e / s2;
        }
    }
    __syncthreads();

    if (widx < 12) {
        const int h = widx >> 1, sub = widx & 1;
        const float* vf = qsf + (2 * CDIM + h * 32) * 66;
        const float* attn_s = stf + h * 1024;

        // cache v columns (px-pair = lane) packed
        ULL vc[32];
        #pragma unroll
        for (int d = 0; d < 32; ++d)
            vc[d] = *(const ULL*)(vf + d * 66 + lane * 2);

        for (int r = 0; r < 16; ++r) {
            const int r0 = sub * 16 + r;
            ULL o2 = 0ull;
            #pragma unroll
            for (int d = 0; d < 32; ++d) {
                ULL ad = dup2(attn_s[r0 * 32 + d]);   // broadcast + dup
                ffma2(o2, ad, vc[d]);
            }
            *(ULL*)(aof + ((h * 32 + r0) * 32 + lane) * 2) = o2;
        }
    }
    __syncthreads();

    // ---- project_out 1x1 (192x192 GEMM), 3 chunks of 64, store with +SHIFT roll ----
    for (int chk = 0; chk < 3; ++chk) {
        const int ocb = chk * 64;
        ULL acc[4];
        gemm64(g_proj_wd, CDIM, ocb, aof, acc, tid);
        const int gh  = (h0 + (po2 >> 3)) & 255;
        const int gh2 = (gh + 4) & 255;
        const int gw  = (w0 + (po2 & 7)) & 255;
        #pragma unroll
        for (int j = 0; j < 4; ++j) {
            const int oc = ocb + ocg * 4 + j;
            float2 v = asf2(acc[j]);
            float* base = out + (size_t)(b * CDIM + oc) * HWDIM * HWDIM;
            base[gh * HWDIM + gw]  = v.x;
            base[gh2 * HWDIM + gw] = v.y;
        }
    }
}

extern "C" void kernel_launch(void* const* d_in, const int* in_sizes, int n_in,
                              void* d_out, int out_size)
{
    const float* x           = (const float*)d_in[0];
    const float* qkv_w       = (const float*)d_in[1];
    const float* dw_w        = (const float*)d_in[2];
    const float* proj_w      = (const float*)d_in[3];
    const float* temperature = (const float*)d_in[4];
    float* out               = (float*)d_out;

    const int prep_n = CDIM * OC3 + CDIM * CDIM;
    prep_weights<<<(prep_n + 255) / 256, 256>>>(qkv_w, proj_w);

    const size_t smem_bytes = (size_t)SMEM_FLOATS * sizeof(float);
    cudaFuncSetAttribute(win_attn_kernel,
                         cudaFuncAttributeMaxDynamicSharedMemorySize,
                         (int)smem_bytes);
    win_attn_kernel<<<NWIN, 512, smem_bytes>>>(x, dw_w, temperature, out);
}